// round 16
// baseline (speedup 1.0000x reference)
#include <cuda_runtime.h>
#include <cuda_fp16.h>
#include <math.h>
#include <stdint.h>

// ---------------- problem constants ----------------
#define BSZ  4096
#define NCLS 1000
#define BO   4096
#define NCOL (BSZ+NCLS+BO)    // 9192
#define NPAD 9216             // padded to 256
#define DD   512
#define INV_T 10.0f
#define SHIFT 10.0f

// ---------------- tiling ----------------
#define M_TILE 64
#define N_TILE 256
#define KCH    64                  // k-chunk: 64 fp16 = 128 B rows
#define NKC    (DD/KCH)            // 8
#define MT     (BSZ/M_TILE)        // 64
#define NT     (NPAD/N_TILE)       // 36

// smem: 2-stage pipeline, 40 KB per stage (A 8K + B 32K) -> 80 KB/CTA, 2 CTAs/SM
#define T_AH 0
#define T_BH 8192
#define BUF_SZ 40960
#define SMEM_SZ (2*BUF_SZ)         // 80 KB

#define SWZ(x) ((x) ^ (((x)>>3)&0x70))

// partial slots per row: [0,36) col-tile partials, [36,100) mirror partials (bx<=59 used)
#define PSLOTS 128
#define PLIVE  100
#define PMIR   36

#define CONV_BLOCKS ((NPAD*(DD/8))/256)   // 2304

// ---------------- device scratch ----------------
__device__ __half g_hi[(size_t)NPAD*DD];
__device__ int   g_cntB[NCLS];
__device__ int   g_lbl[NPAD];
__device__ float g_inv0[NPAD];
__device__ float g_inv1[NPAD];
__device__ float2 g_part[(size_t)BSZ*PSLOTS];   // (s1, den) pairs; zero-init .bss, unused slots never written
__device__ float g_rowv[BSZ];

// ---------------- ptx helpers (base-PTX sm_80-era ops only) ----------------
__device__ __forceinline__ uint32_t s2u(const void* p) {
    uint32_t a;
    asm("{ .reg .u64 t; cvta.to.shared.u64 t, %1; cvt.u32.u64 %0, t; }" : "=r"(a) : "l"(p));
    return a;
}
__device__ __forceinline__ void ldsm4(uint32_t* r, uint32_t addr) {
    asm volatile("ldmatrix.sync.aligned.m8n8.x4.shared.b16 {%0,%1,%2,%3}, [%4];"
        : "=r"(r[0]), "=r"(r[1]), "=r"(r[2]), "=r"(r[3]) : "r"(addr));
}
__device__ __forceinline__ void mma16816h(uint32_t* c, const uint32_t* a, uint32_t b0, uint32_t b1) {
    asm volatile("mma.sync.aligned.m16n8k16.row.col.f16.f16.f16.f16 "
        "{%0,%1}, {%2,%3,%4,%5}, {%6,%7}, {%0,%1};"
        : "+r"(c[0]), "+r"(c[1])
        : "r"(a[0]), "r"(a[1]), "r"(a[2]), "r"(a[3]), "r"(b0), "r"(b1));
}
__device__ __forceinline__ void cp16(uint32_t dst, const void* src) {
    asm volatile("cp.async.cg.shared.global [%0], [%1], 16;" :: "r"(dst), "l"(src) : "memory");
}

// ---------------- fused setup: conv blocks + one prep block (concurrent) ----------------
__global__ void k_prepconv(const float* __restrict__ centers, const float* __restrict__ feats,
                           const float* __restrict__ food,
                           const int* __restrict__ targets, const int* __restrict__ pseudo) {
    const int tid = threadIdx.x;

    if (blockIdx.x == CONV_BLOCKS) {
        // ---- prep: histograms + per-column tables (one 256-thread CTA) ----
        __shared__ int sAll[NCLS];
        __shared__ int sB[NCLS];
        for (int i = tid; i < NCLS; i += 256) { sAll[i] = 1; sB[i] = 0; }  // +1 per class center
        __syncthreads();
        for (int i = tid; i < BSZ; i += 256) {
            int t = targets[i];
            atomicAdd(&sB[t], 1);
            atomicAdd(&sAll[t], 1);
        }
        for (int i = tid; i < BO; i += 256) atomicAdd(&sAll[pseudo[i]], 1);
        __syncthreads();
        for (int i = tid; i < NCLS; i += 256) g_cntB[i] = sB[i];
        for (int j = tid; j < NPAD; j += 256) {
            int lbl, cls;
            if (j < BSZ)           { lbl = targets[j];  cls = lbl; }
            else if (j < BSZ+NCLS) { lbl = j - BSZ;     cls = lbl; }
            else if (j < NCOL)     { lbl = NCLS;        cls = pseudo[j-BSZ-NCLS]; }
            else { g_lbl[j] = -1; g_inv0[j] = 0.f; g_inv1[j] = 0.f; continue; }
            float w0 = (float)sAll[cls];
            g_lbl[j]  = lbl;
            g_inv0[j] = 1.0f / w0;
            g_inv1[j] = (w0 > 1.5f) ? 1.0f / (w0 - 1.0f) : 0.f;
        }
        return;
    }

    // ---- conv: fp16 conversion, 8 floats -> 8 halfs (16B store) per thread ----
    int v = blockIdx.x * 256 + tid;
    int j = v >> 6;
    int k = (v & 63) * 8;
    const float* src;
    if (j < BSZ)            src = feats   + (((size_t)j) << 9) + k;
    else if (j < BSZ+NCLS)  src = centers + (((size_t)(j-BSZ)) << 9) + k;
    else if (j < NCOL)      src = food    + (((size_t)(j-BSZ-NCLS)) << 9) + k;
    else                    src = nullptr;

    uint4 outv;
    if (src) {
        float4 f0 = *(const float4*)src;
        float4 f1 = *(const float4*)(src + 4);
        __half2 h0 = __floats2half2_rn(f0.x, f0.y);
        __half2 h1 = __floats2half2_rn(f0.z, f0.w);
        __half2 h2 = __floats2half2_rn(f1.x, f1.y);
        __half2 h3 = __floats2half2_rn(f1.z, f1.w);
        outv = make_uint4(*(uint32_t*)&h0, *(uint32_t*)&h1, *(uint32_t*)&h2, *(uint32_t*)&h3);
    } else {
        outv = make_uint4(0u, 0u, 0u, 0u);
    }
    ((uint4*)g_hi)[v] = outv;
}

// ---------------- main HMMA GEMM (fp16, f16-accum, symmetric-skip) + fused epilogue ----------------
__global__ __launch_bounds__(256, 2)
void k_main(const int* __restrict__ targets) {
    if (((blockIdx.y + 1) << 2) <= blockIdx.x) return;   // lower tile: mirrored elsewhere

    extern __shared__ __align__(1024) char sm[];
    const uint32_t sb = s2u(sm);
    const int tid  = threadIdx.x;
    const int wid  = tid >> 5;
    const int lane = tid & 31;
    const int warpM = wid & 1;       // 2 row groups of 32
    const int warpN = wid >> 1;      // 4 col groups of 64
    const int rowBase = blockIdx.x * M_TILE;
    const int colBase = blockIdx.y * N_TILE;
    const bool isUp = (blockIdx.x + 1 <= 4 * blockIdx.y) && (blockIdx.y < 16);

    uint32_t acc[2][8][2];           // packed half2 x2 per 16x8 fragment
    #pragma unroll
    for (int a = 0; a < 2; a++)
        #pragma unroll
        for (int b = 0; b < 8; b++) { acc[a][b][0] = 0u; acc[a][b][1] = 0u; }

    auto load_chunk = [&](int c) {
        const uint32_t bo = (uint32_t)(c & 1) * BUF_SZ;
        const int kb = c * KCH;
        #pragma unroll
        for (int i = 0; i < 10; i++) {
            int q   = tid + i * 256;
            int seg = q & 7;
            int u   = q >> 3;
            uint32_t tOff; int lr, gr;
            if (u < 64)  { lr = u;      gr = rowBase + lr; tOff = T_AH; }
            else         { lr = u - 64; gr = colBase + lr; tOff = T_BH; }
            uint32_t off = (uint32_t)lr * 128 + (uint32_t)seg * 16;
            cp16(sb + bo + tOff + SWZ(off), g_hi + (((size_t)gr) << 9) + kb + seg * 8);
        }
        asm volatile("cp.async.commit_group;" ::: "memory");
    };

    const int lr15 = lane & 15;
    const int lk   = (lane >> 4) * 16;

    load_chunk(0);

    #pragma unroll 1
    for (int c = 0; c < NKC; ++c) {
        if (c + 1 < NKC) {
            load_chunk(c + 1);
            asm volatile("cp.async.wait_group 1;" ::: "memory");
        } else {
            asm volatile("cp.async.wait_group 0;" ::: "memory");
        }
        __syncthreads();

        const uint32_t bo = (uint32_t)(c & 1) * BUF_SZ;
        #pragma unroll
        for (int ks = 0; ks < 4; ++ks) {
            uint32_t aH[2][4];
            #pragma unroll
            for (int mb = 0; mb < 2; ++mb) {
                uint32_t ro = (uint32_t)(warpM * 32 + mb * 16 + lr15) * 128 + ks * 32 + lk;
                ldsm4(aH[mb], sb + bo + T_AH + SWZ(ro));
            }
            #pragma unroll
            for (int ns = 0; ns < 2; ++ns) {
                uint32_t bH[2][4];
                #pragma unroll
                for (int g = 0; g < 2; ++g) {
                    uint32_t co = (uint32_t)(warpN * 64 + ns * 32 + g * 16 + lr15) * 128 + ks * 32 + lk;
                    ldsm4(bH[g], sb + bo + T_BH + SWZ(co));
                }
                #pragma unroll
                for (int mb = 0; mb < 2; ++mb)
                    #pragma unroll
                    for (int g = 0; g < 2; ++g)
                        #pragma unroll
                        for (int h = 0; h < 2; ++h)
                            mma16816h(acc[mb][ns * 4 + g * 2 + h], aH[mb], bH[g][h], bH[g][h + 2]);
            }
        }
        __syncthreads();
    }

    // ---- epilogue ----
    const int groupID = lane >> 2;
    const int tig     = lane & 3;

    int rows[4], myL[4];
    float rI0[4], rI1[4];
    #pragma unroll
    for (int mb = 0; mb < 2; ++mb)
        #pragma unroll
        for (int rh = 0; rh < 2; ++rh) {
            int r = rowBase + warpM * 32 + mb * 16 + groupID + rh * 8;
            int idx = mb * 2 + rh;
            rows[idx] = r;
            myL [idx] = targets[r];
            rI0 [idx] = g_inv0[r];
            rI1 [idx] = g_inv1[r];
        }

    float den[4], s1[4];
    #pragma unroll
    for (int r = 0; r < 4; ++r) { den[r] = 0.f; s1[r] = 0.f; }
    float cden[16], cs1[16];
    #pragma unroll
    for (int k = 0; k < 16; ++k) { cden[k] = 0.f; cs1[k] = 0.f; }

    #pragma unroll
    for (int nb = 0; nb < 8; ++nb) {
        #pragma unroll
        for (int j2 = 0; j2 < 2; ++j2) {
            const int col = colBase + warpN * 64 + nb * 8 + tig * 2 + j2;
            const int   cl = g_lbl[col];
            const float v0 = g_inv0[col];
            const float v1 = g_inv1[col];
            #pragma unroll
            for (int mb = 0; mb < 2; ++mb)
                #pragma unroll
                for (int rh = 0; rh < 2; ++rh) {
                    const int idx = mb * 2 + rh;
                    __half2 hv = *(__half2*)&acc[mb][nb][rh];
                    float dval = (j2 == 0) ? __low2float(hv) : __high2float(hv);
                    float logit = dval * INV_T;
                    float p = __expf(logit - SHIFT);
                    bool self = (col == rows[idx]);
                    bool m = (cl == myL[idx]) && !self;
                    if (!self) den[idx] += p * (m ? v1 : v0);
                    if (m)     s1[idx]  += logit;
                    if (isUp) {
                        cden[nb*2+j2] += p * (m ? rI1[idx] : rI0[idx]);
                        if (m) cs1[nb*2+j2] += logit;
                    }
                }
        }
    }

    #pragma unroll
    for (int r = 0; r < 4; ++r) {
        den[r] += __shfl_xor_sync(0xFFFFFFFFu, den[r], 1);
        den[r] += __shfl_xor_sync(0xFFFFFFFFu, den[r], 2);
        s1[r]  += __shfl_xor_sync(0xFFFFFFFFu, s1[r],  1);
        s1[r]  += __shfl_xor_sync(0xFFFFFFFFu, s1[r],  2);
    }

    float* sden  = (float*)sm;             // [64][4]
    float* ss1   = (float*)(sm + 1024);    // [64][4]
    float* cbufD = (float*)(sm + 4096);    // [2][256]
    float* cbufS = (float*)(sm + 8192);    // [2][256]
    if (tig == 0) {
        #pragma unroll
        for (int mb = 0; mb < 2; ++mb)
            #pragma unroll
            for (int rh = 0; rh < 2; ++rh) {
                int rl = warpM * 32 + mb * 16 + groupID + rh * 8;
                sden[rl * 4 + warpN] = den[mb * 2 + rh];
                ss1 [rl * 4 + warpN] = s1 [mb * 2 + rh];
            }
    }

    if (isUp) {
        #pragma unroll
        for (int k = 0; k < 16; ++k) {
            cden[k] += __shfl_xor_sync(0xFFFFFFFFu, cden[k], 4);
            cden[k] += __shfl_xor_sync(0xFFFFFFFFu, cden[k], 8);
            cden[k] += __shfl_xor_sync(0xFFFFFFFFu, cden[k], 16);
            cs1[k]  += __shfl_xor_sync(0xFFFFFFFFu, cs1[k],  4);
            cs1[k]  += __shfl_xor_sync(0xFFFFFFFFu, cs1[k],  8);
            cs1[k]  += __shfl_xor_sync(0xFFFFFFFFu, cs1[k],  16);
        }
        if (lane < 4) {
            #pragma unroll
            for (int nb = 0; nb < 8; ++nb)
                #pragma unroll
                for (int j2 = 0; j2 < 2; ++j2) {
                    int cc = warpN * 64 + nb * 8 + lane * 2 + j2;
                    cbufD[warpM * 256 + cc] = cden[nb*2+j2];
                    cbufS[warpM * 256 + cc] = cs1 [nb*2+j2];
                }
        }
    }
    __syncthreads();

    // transposed partial writes: g_part[row][slot] = (s1, den)
    if (tid < 64) {
        float d = sden[tid*4] + sden[tid*4+1] + sden[tid*4+2] + sden[tid*4+3];
        float s = ss1 [tid*4] + ss1 [tid*4+1] + ss1 [tid*4+2] + ss1 [tid*4+3];
        g_part[(size_t)(rowBase + tid) * PSLOTS + blockIdx.y] = make_float2(s, d);
    }
    if (isUp) {
        g_part[(size_t)(colBase + tid) * PSLOTS + PMIR + blockIdx.x] =
            make_float2(cbufS[tid] + cbufS[256 + tid], cbufD[tid] + cbufD[256 + tid]);
    }
}

// ---------------- per-row combine: one warp per row, coalesced float2 reads ----------------
__global__ void k_rows(const int* __restrict__ targets) {
    const int gt   = blockIdx.x * blockDim.x + threadIdx.x;
    const int row  = gt >> 5;
    const int lane = gt & 31;
    if (row >= BSZ) return;
    const float2* p = g_part + (size_t)row * PSLOTS;
    float s1 = 0.f, den = 0.f;
    #pragma unroll
    for (int o = 0; o < PLIVE + 31; o += 32) {      // slots >= PLIVE are never written
        if (o + lane < PLIVE) {
            float2 v = p[o + lane];
            s1 += v.x; den += v.y;
        }
    }
    #pragma unroll
    for (int o = 16; o > 0; o >>= 1) {
        s1  += __shfl_xor_sync(0xFFFFFFFFu, s1,  o);
        den += __shfl_xor_sync(0xFFFFFFFFu, den, o);
    }
    if (lane == 0) {
        float npos = (float)g_cntB[targets[row]];
        g_rowv[row] = s1 / npos - SHIFT - logf(den);
    }
}

// ---------------- final scalar reduction ----------------
__global__ void k_final(float* __restrict__ out) {
    __shared__ float sred[256];
    float local = 0.f;
    for (int i = threadIdx.x; i < BSZ; i += 256) local += g_rowv[i];
    sred[threadIdx.x] = local;
    __syncthreads();
    for (int o = 128; o > 0; o >>= 1) {
        if (threadIdx.x < o) sred[threadIdx.x] += sred[threadIdx.x + o];
        __syncthreads();
    }
    if (threadIdx.x == 0) out[0] = -sred[0] / (float)BSZ;
}

// ---------------- launch ----------------
extern "C" void kernel_launch(void* const* d_in, const int* in_sizes, int n_in,
                              void* d_out, int out_size) {
    const float* centers = (const float*)d_in[0];
    const float* feats   = (const float*)d_in[1];
    const int*   targets = (const int*)  d_in[2];
    const float* food    = (const float*)d_in[3];
    const int*   pseudo  = (const int*)  d_in[4];
    float* out = (float*)d_out;

    cudaFuncSetAttribute(k_main, cudaFuncAttributeMaxDynamicSharedMemorySize, SMEM_SZ);

    k_prepconv<<<CONV_BLOCKS + 1, 256>>>(centers, feats, food, targets, pseudo);
    dim3 grid(MT, NT);
    k_main<<<grid, 256, SMEM_SZ>>>(targets);
    k_rows<<<(BSZ * 32) / 256, 256>>>(targets);
    k_final<<<1, 256>>>(out);
}

// round 17
// speedup vs baseline: 1.1046x; 1.1046x over previous
#include <cuda_runtime.h>
#include <cuda_fp16.h>
#include <math.h>
#include <stdint.h>

// ---------------- problem constants ----------------
#define BSZ  4096
#define NCLS 1000
#define BO   4096
#define NCOL (BSZ+NCLS+BO)    // 9192
#define NPAD 9216             // padded to 256
#define DD   512
#define INV_T 10.0f
#define SHIFT 10.0f

// ---------------- tiling ----------------
#define M_TILE 64
#define N_TILE 256
#define KCH    64                  // k-chunk: 64 fp16 = 128 B rows
#define NKC    (DD/KCH)            // 8
#define MT     (BSZ/M_TILE)        // 64
#define NT     (NPAD/N_TILE)       // 36

// smem: 2-stage pipeline, 40 KB per stage (A 8K + B 32K) -> 80 KB/CTA, 2 CTAs/SM
#define T_AH 0
#define T_BH 8192
#define BUF_SZ 40960
#define SMEM_SZ (2*BUF_SZ)         // 80 KB

#define SWZ(x) ((x) ^ (((x)>>3)&0x70))

// partial slots per row: [0,36) col-tile partials, [36,100) mirror partials (bx<=59 used)
#define PSLOTS 128
#define PLIVE  100
#define PMIR   36

// ---------------- device scratch ----------------
__device__ __half g_hi[(size_t)NPAD*DD];
__device__ int   g_cntB[NCLS];
__device__ int   g_lbl[NPAD];
__device__ float g_inv0[NPAD];
__device__ float g_inv1[NPAD];
__device__ float2 g_part[(size_t)BSZ*PSLOTS];   // (s1, den) pairs; zero-init .bss, unused slots never written
__device__ float g_rowv[BSZ];

// ---------------- ptx helpers (base-PTX sm_80-era ops only) ----------------
__device__ __forceinline__ uint32_t s2u(const void* p) {
    uint32_t a;
    asm("{ .reg .u64 t; cvta.to.shared.u64 t, %1; cvt.u32.u64 %0, t; }" : "=r"(a) : "l"(p));
    return a;
}
__device__ __forceinline__ void ldsm4(uint32_t* r, uint32_t addr) {
    asm volatile("ldmatrix.sync.aligned.m8n8.x4.shared.b16 {%0,%1,%2,%3}, [%4];"
        : "=r"(r[0]), "=r"(r[1]), "=r"(r[2]), "=r"(r[3]) : "r"(addr));
}
__device__ __forceinline__ void mma16816h(uint32_t* c, const uint32_t* a, uint32_t b0, uint32_t b1) {
    asm volatile("mma.sync.aligned.m16n8k16.row.col.f16.f16.f16.f16 "
        "{%0,%1}, {%2,%3,%4,%5}, {%6,%7}, {%0,%1};"
        : "+r"(c[0]), "+r"(c[1])
        : "r"(a[0]), "r"(a[1]), "r"(a[2]), "r"(a[3]), "r"(b0), "r"(b1));
}
__device__ __forceinline__ void cp16(uint32_t dst, const void* src) {
    asm volatile("cp.async.cg.shared.global [%0], [%1], 16;" :: "r"(dst), "l"(src) : "memory");
}

// ---------------- fused setup: histogram + per-column tables (single CTA, 1024 thr) ----------------
__global__ void k_prep(const int* __restrict__ targets, const int* __restrict__ pseudo) {
    __shared__ int sAll[NCLS];
    __shared__ int sB[NCLS];
    const int tid = threadIdx.x;
    for (int i = tid; i < NCLS; i += 1024) { sAll[i] = 1; sB[i] = 0; }  // +1 per class center
    __syncthreads();
    for (int i = tid; i < BSZ; i += 1024) {
        int t = targets[i];
        atomicAdd(&sB[t], 1);
        atomicAdd(&sAll[t], 1);
    }
    for (int i = tid; i < BO; i += 1024) atomicAdd(&sAll[pseudo[i]], 1);
    __syncthreads();
    for (int i = tid; i < NCLS; i += 1024) g_cntB[i] = sB[i];
    for (int j = tid; j < NPAD; j += 1024) {
        int lbl, cls;
        if (j < BSZ)           { lbl = targets[j];  cls = lbl; }
        else if (j < BSZ+NCLS) { lbl = j - BSZ;     cls = lbl; }
        else if (j < NCOL)     { lbl = NCLS;        cls = pseudo[j-BSZ-NCLS]; }
        else { g_lbl[j] = -1; g_inv0[j] = 0.f; g_inv1[j] = 0.f; continue; }
        float w0 = (float)sAll[cls];
        g_lbl[j]  = lbl;
        g_inv0[j] = 1.0f / w0;
        g_inv1[j] = (w0 > 1.5f) ? 1.0f / (w0 - 1.0f) : 0.f;
    }
}

// fp16 conversion of features_all (pad rows -> 0); 8 floats -> 8 halfs (16B store) per thread
__global__ void k_conv(const float* __restrict__ centers, const float* __restrict__ feats,
                       const float* __restrict__ food) {
    int v = blockIdx.x * blockDim.x + threadIdx.x;     // one per 8-elem group
    if (v >= NPAD * (DD/8)) return;
    int j = v >> 6;
    int k = (v & 63) * 8;
    const float* src;
    if (j < BSZ)            src = feats   + (((size_t)j) << 9) + k;
    else if (j < BSZ+NCLS)  src = centers + (((size_t)(j-BSZ)) << 9) + k;
    else if (j < NCOL)      src = food    + (((size_t)(j-BSZ-NCLS)) << 9) + k;
    else                    src = nullptr;

    uint4 outv;
    if (src) {
        float4 f0 = *(const float4*)src;
        float4 f1 = *(const float4*)(src + 4);
        __half2 h0 = __floats2half2_rn(f0.x, f0.y);
        __half2 h1 = __floats2half2_rn(f0.z, f0.w);
        __half2 h2 = __floats2half2_rn(f1.x, f1.y);
        __half2 h3 = __floats2half2_rn(f1.z, f1.w);
        outv = make_uint4(*(uint32_t*)&h0, *(uint32_t*)&h1, *(uint32_t*)&h2, *(uint32_t*)&h3);
    } else {
        outv = make_uint4(0u, 0u, 0u, 0u);
    }
    ((uint4*)g_hi)[v] = outv;
}

// ---------------- main HMMA GEMM (fp16, f16-accum, symmetric-skip) + fused epilogue ----------------
__global__ __launch_bounds__(256, 2)
void k_main(const int* __restrict__ targets) {
    if (((blockIdx.y + 1) << 2) <= blockIdx.x) return;   // lower tile: mirrored elsewhere

    extern __shared__ __align__(1024) char sm[];
    const uint32_t sb = s2u(sm);
    const int tid  = threadIdx.x;
    const int wid  = tid >> 5;
    const int lane = tid & 31;
    const int warpM = wid & 1;       // 2 row groups of 32
    const int warpN = wid >> 1;      // 4 col groups of 64
    const int rowBase = blockIdx.x * M_TILE;
    const int colBase = blockIdx.y * N_TILE;
    const bool isUp = (blockIdx.x + 1 <= 4 * blockIdx.y) && (blockIdx.y < 16);

    uint32_t acc[2][8][2];           // packed half2 x2 per 16x8 fragment
    #pragma unroll
    for (int a = 0; a < 2; a++)
        #pragma unroll
        for (int b = 0; b < 8; b++) { acc[a][b][0] = 0u; acc[a][b][1] = 0u; }

    auto load_chunk = [&](int c) {
        const uint32_t bo = (uint32_t)(c & 1) * BUF_SZ;
        const int kb = c * KCH;
        #pragma unroll
        for (int i = 0; i < 10; i++) {
            int q   = tid + i * 256;
            int seg = q & 7;
            int u   = q >> 3;
            uint32_t tOff; int lr, gr;
            if (u < 64)  { lr = u;      gr = rowBase + lr; tOff = T_AH; }
            else         { lr = u - 64; gr = colBase + lr; tOff = T_BH; }
            uint32_t off = (uint32_t)lr * 128 + (uint32_t)seg * 16;
            cp16(sb + bo + tOff + SWZ(off), g_hi + (((size_t)gr) << 9) + kb + seg * 8);
        }
        asm volatile("cp.async.commit_group;" ::: "memory");
    };

    const int lr15 = lane & 15;
    const int lk   = (lane >> 4) * 16;

    load_chunk(0);

    #pragma unroll 1
    for (int c = 0; c < NKC; ++c) {
        if (c + 1 < NKC) {
            load_chunk(c + 1);
            asm volatile("cp.async.wait_group 1;" ::: "memory");
        } else {
            asm volatile("cp.async.wait_group 0;" ::: "memory");
        }
        __syncthreads();

        const uint32_t bo = (uint32_t)(c & 1) * BUF_SZ;
        #pragma unroll
        for (int ks = 0; ks < 4; ++ks) {
            uint32_t aH[2][4];
            #pragma unroll
            for (int mb = 0; mb < 2; ++mb) {
                uint32_t ro = (uint32_t)(warpM * 32 + mb * 16 + lr15) * 128 + ks * 32 + lk;
                ldsm4(aH[mb], sb + bo + T_AH + SWZ(ro));
            }
            #pragma unroll
            for (int ns = 0; ns < 2; ++ns) {
                uint32_t bH[2][4];
                #pragma unroll
                for (int g = 0; g < 2; ++g) {
                    uint32_t co = (uint32_t)(warpN * 64 + ns * 32 + g * 16 + lr15) * 128 + ks * 32 + lk;
                    ldsm4(bH[g], sb + bo + T_BH + SWZ(co));
                }
                #pragma unroll
                for (int mb = 0; mb < 2; ++mb)
                    #pragma unroll
                    for (int g = 0; g < 2; ++g)
                        #pragma unroll
                        for (int h = 0; h < 2; ++h)
                            mma16816h(acc[mb][ns * 4 + g * 2 + h], aH[mb], bH[g][h], bH[g][h + 2]);
            }
        }
        __syncthreads();
    }

    // ---- epilogue ----
    const int groupID = lane >> 2;
    const int tig     = lane & 3;

    int rows[4], myL[4];
    float rI0[4], rI1[4];
    #pragma unroll
    for (int mb = 0; mb < 2; ++mb)
        #pragma unroll
        for (int rh = 0; rh < 2; ++rh) {
            int r = rowBase + warpM * 32 + mb * 16 + groupID + rh * 8;
            int idx = mb * 2 + rh;
            rows[idx] = r;
            myL [idx] = targets[r];
            rI0 [idx] = g_inv0[r];
            rI1 [idx] = g_inv1[r];
        }

    float den[4], s1[4];
    #pragma unroll
    for (int r = 0; r < 4; ++r) { den[r] = 0.f; s1[r] = 0.f; }
    float cden[16], cs1[16];
    #pragma unroll
    for (int k = 0; k < 16; ++k) { cden[k] = 0.f; cs1[k] = 0.f; }

    #pragma unroll
    for (int nb = 0; nb < 8; ++nb) {
        #pragma unroll
        for (int j2 = 0; j2 < 2; ++j2) {
            const int col = colBase + warpN * 64 + nb * 8 + tig * 2 + j2;
            const int   cl = g_lbl[col];
            const float v0 = g_inv0[col];
            const float v1 = g_inv1[col];
            #pragma unroll
            for (int mb = 0; mb < 2; ++mb)
                #pragma unroll
                for (int rh = 0; rh < 2; ++rh) {
                    const int idx = mb * 2 + rh;
                    __half2 hv = *(__half2*)&acc[mb][nb][rh];
                    float dval = (j2 == 0) ? __low2float(hv) : __high2float(hv);
                    float logit = dval * INV_T;
                    float p = __expf(logit - SHIFT);
                    bool self = (col == rows[idx]);
                    bool m = (cl == myL[idx]) && !self;
                    if (!self) den[idx] += p * (m ? v1 : v0);
                    if (m)     s1[idx]  += logit;
                    if (isUp) {
                        cden[nb*2+j2] += p * (m ? rI1[idx] : rI0[idx]);
                        if (m) cs1[nb*2+j2] += logit;
                    }
                }
        }
    }

    #pragma unroll
    for (int r = 0; r < 4; ++r) {
        den[r] += __shfl_xor_sync(0xFFFFFFFFu, den[r], 1);
        den[r] += __shfl_xor_sync(0xFFFFFFFFu, den[r], 2);
        s1[r]  += __shfl_xor_sync(0xFFFFFFFFu, s1[r],  1);
        s1[r]  += __shfl_xor_sync(0xFFFFFFFFu, s1[r],  2);
    }

    float* sden  = (float*)sm;             // [64][4]
    float* ss1   = (float*)(sm + 1024);    // [64][4]
    float* cbufD = (float*)(sm + 4096);    // [2][256]
    float* cbufS = (float*)(sm + 8192);    // [2][256]
    if (tig == 0) {
        #pragma unroll
        for (int mb = 0; mb < 2; ++mb)
            #pragma unroll
            for (int rh = 0; rh < 2; ++rh) {
                int rl = warpM * 32 + mb * 16 + groupID + rh * 8;
                sden[rl * 4 + warpN] = den[mb * 2 + rh];
                ss1 [rl * 4 + warpN] = s1 [mb * 2 + rh];
            }
    }

    if (isUp) {
        #pragma unroll
        for (int k = 0; k < 16; ++k) {
            cden[k] += __shfl_xor_sync(0xFFFFFFFFu, cden[k], 4);
            cden[k] += __shfl_xor_sync(0xFFFFFFFFu, cden[k], 8);
            cden[k] += __shfl_xor_sync(0xFFFFFFFFu, cden[k], 16);
            cs1[k]  += __shfl_xor_sync(0xFFFFFFFFu, cs1[k],  4);
            cs1[k]  += __shfl_xor_sync(0xFFFFFFFFu, cs1[k],  8);
            cs1[k]  += __shfl_xor_sync(0xFFFFFFFFu, cs1[k],  16);
        }
        if (lane < 4) {
            #pragma unroll
            for (int nb = 0; nb < 8; ++nb)
                #pragma unroll
                for (int j2 = 0; j2 < 2; ++j2) {
                    int cc = warpN * 64 + nb * 8 + lane * 2 + j2;
                    cbufD[warpM * 256 + cc] = cden[nb*2+j2];
                    cbufS[warpM * 256 + cc] = cs1 [nb*2+j2];
                }
        }
    }
    __syncthreads();

    // transposed partial writes: g_part[row][slot] = (s1, den)
    if (tid < 64) {
        float d = sden[tid*4] + sden[tid*4+1] + sden[tid*4+2] + sden[tid*4+3];
        float s = ss1 [tid*4] + ss1 [tid*4+1] + ss1 [tid*4+2] + ss1 [tid*4+3];
        g_part[(size_t)(rowBase + tid) * PSLOTS + blockIdx.y] = make_float2(s, d);
    }
    if (isUp) {
        g_part[(size_t)(colBase + tid) * PSLOTS + PMIR + blockIdx.x] =
            make_float2(cbufS[tid] + cbufS[256 + tid], cbufD[tid] + cbufD[256 + tid]);
    }
}

// ---------------- per-row combine: one warp per row, coalesced float2 reads ----------------
__global__ void k_rows(const int* __restrict__ targets) {
    const int gt   = blockIdx.x * blockDim.x + threadIdx.x;
    const int row  = gt >> 5;
    const int lane = gt & 31;
    if (row >= BSZ) return;
    const float2* p = g_part + (size_t)row * PSLOTS;
    float s1 = 0.f, den = 0.f;
    #pragma unroll
    for (int o = 0; o < PLIVE + 31; o += 32) {      // slots >= PLIVE are never written
        if (o + lane < PLIVE) {
            float2 v = p[o + lane];
            s1 += v.x; den += v.y;
        }
    }
    #pragma unroll
    for (int o = 16; o > 0; o >>= 1) {
        s1  += __shfl_xor_sync(0xFFFFFFFFu, s1,  o);
        den += __shfl_xor_sync(0xFFFFFFFFu, den, o);
    }
    if (lane == 0) {
        float npos = (float)g_cntB[targets[row]];
        g_rowv[row] = s1 / npos - SHIFT - logf(den);
    }
}

// ---------------- final scalar reduction (1024 threads, short serial path) ----------------
__global__ void k_final(float* __restrict__ out) {
    __shared__ float sred[1024];
    float local = 0.f;
    for (int i = threadIdx.x; i < BSZ; i += 1024) local += g_rowv[i];
    sred[threadIdx.x] = local;
    __syncthreads();
    for (int o = 512; o > 0; o >>= 1) {
        if (threadIdx.x < o) sred[threadIdx.x] += sred[threadIdx.x + o];
        __syncthreads();
    }
    if (threadIdx.x == 0) out[0] = -sred[0] / (float)BSZ;
}

// ---------------- launch ----------------
extern "C" void kernel_launch(void* const* d_in, const int* in_sizes, int n_in,
                              void* d_out, int out_size) {
    const float* centers = (const float*)d_in[0];
    const float* feats   = (const float*)d_in[1];
    const int*   targets = (const int*)  d_in[2];
    const float* food    = (const float*)d_in[3];
    const int*   pseudo  = (const int*)  d_in[4];
    float* out = (float*)d_out;

    cudaFuncSetAttribute(k_main, cudaFuncAttributeMaxDynamicSharedMemorySize, SMEM_SZ);

    k_prep<<<1, 1024>>>(targets, pseudo);
    k_conv<<<(NPAD * (DD/8)) / 256, 256>>>(centers, feats, food);
    dim3 grid(MT, NT);
    k_main<<<grid, 256, SMEM_SZ>>>(targets);
    k_rows<<<(BSZ * 32) / 256, 256>>>(targets);
    k_final<<<1, 1024>>>(out);
}